// round 13
// baseline (speedup 1.0000x reference)
#include <cuda_runtime.h>
#include <math.h>

// ---------------- problem constants ----------------
#define Bsz    16
#define CIN    103
#define CCONV  256
#define NOUT   103
#define DOUT   16
#define RECN   8343            // 9*9*103
#define H1N    5562
#define H2N    12514
#define F0N    1648            // NOUT*DOUT
#define NCH    15              // conv ci-chunks (7 channels each)
#define TN     512             // GEMM columns per block

// ---------------- scratch (device globals; no allocation) ----------------
__device__ float g_wT[927 * 256];              // transposed conv weights [e=ci*9+k][co]
__device__ float g_Wsum[CCONV * NOUT * DOUT];  // sum over prim axis of W_caps
__device__ float g_part[Bsz * NCH * CCONV * 49];
__device__ float g_hsum[Bsz * CCONV * 49];     // relu'd conv activations
__device__ float g_sq[Bsz * CCONV];
__device__ float g_bij[NOUT * CCONV];
__device__ float g_sj[Bsz * NOUT * DOUT];
__device__ float g_v[Bsz * NOUT * DOUT];
__device__ float g_f0[Bsz * F0N];
__device__ float g_f1[Bsz * H1N];
__device__ float g_f2[Bsz * H2N];
// k-split partials. True max across layers:
//   fc1: 52*16*5562  = 4,627,584
//   fc2: 24*16*12514 = 4,805,376  <-- max
//   fc3: 35*16*8343  = 4,672,080
__device__ float g_fcpart[24 * Bsz * H2N + 64];

// packed f32x2 FMA (sm_103a FFMA2 — PTX-only, ptxas never auto-fuses)
#define FMA_F32X2(acc, a, b) \
    asm("fma.rn.f32x2 %0, %1, %2, %0;" : "+l"(acc) : "l"(a), "l"(b))
#define PACK2(dst, w) \
    asm("mov.b64 %0, {%1, %1};" : "=l"(dst) : "f"(w))
#define CP_ASYNC4(dst, src) \
    asm volatile("cp.async.ca.shared.global [%0], [%1], 4;" :: "r"(dst), "l"(src))
#define CP_COMMIT() asm volatile("cp.async.commit_group;")
#define CP_WAIT0()  asm volatile("cp.async.wait_group 0;")
#define CP_WAIT1()  asm volatile("cp.async.wait_group 1;")

// ---------------- small prep kernels ----------------

// conv-weight transpose + routing-logit init fused
__global__ void k_prep(const float* __restrict__ w) {
    int idx = blockIdx.x * 256 + threadIdx.x;
    if (idx < 927 * 256) {
        int e = idx >> 8, co = idx & 255;
        g_wT[idx] = w[co * 927 + e];
    } else {
        int r = idx - 927 * 256;
        if (r < NOUT * CCONV) g_bij[r] = 1.0f;
    }
}

__global__ void k_wsum(const float* __restrict__ Wc) {
    int idx = blockIdx.x * 256 + threadIdx.x;        // 256*103*16
    if (idx < CCONV * NOUT * DOUT) {
        const float4* p = (const float4*)(Wc + (size_t)idx * 32);
        float s = 0.f;
#pragma unroll
        for (int i = 0; i < 8; i++) {
            float4 v = p[i];
            s += v.x + v.y + v.z + v.w;
        }
        g_Wsum[idx] = s;
    }
}

// ---------------- conv (single kernel, weight double-buffer) ----------------
__global__ void __launch_bounds__(256) k_conv(const float* __restrict__ x) {
    int chunk = blockIdx.x, b = blockIdx.y;
    int ci0 = chunk * 7;
    int cnt = min(7, CIN - ci0);
    __shared__ float xs[7 * 81];
    const float* xp = x + (b * CIN + ci0) * 81;
    for (int i = threadIdx.x; i < cnt * 81; i += 256) xs[i] = xp[i];
    __syncthreads();

    int co = threadIdx.x;
    float acc[49];
#pragma unroll
    for (int p = 0; p < 49; p++) acc[p] = 0.f;

    float wA[9], wB[9];
#pragma unroll
    for (int k = 0; k < 9; k++) wA[k] = g_wT[(ci0 * 9 + k) * 256 + co];

    for (int cl = 0; cl < cnt; cl++) {
        if (cl + 1 < cnt) {
#pragma unroll
            for (int k = 0; k < 9; k++)
                wB[k] = g_wT[((ci0 + cl + 1) * 9 + k) * 256 + co];
        }
        const float* xr0 = &xs[cl * 81];
#pragma unroll
        for (int r = 0; r < 9; r++) {
            float xr[9];
#pragma unroll
            for (int q = 0; q < 9; q++) xr[q] = xr0[r * 9 + q];
#pragma unroll
            for (int kh = 0; kh < 3; kh++) {
                int ph = r - kh;
                if (ph >= 0 && ph < 7) {
#pragma unroll
                    for (int pw = 0; pw < 7; pw++) {
#pragma unroll
                        for (int kw = 0; kw < 3; kw++)
                            acc[ph * 7 + pw] = fmaf(wA[kh * 3 + kw], xr[pw + kw], acc[ph * 7 + pw]);
                    }
                }
            }
        }
#pragma unroll
        for (int k = 0; k < 9; k++) wA[k] = wB[k];
    }
    float* outp = &g_part[((b * NCH + chunk) * 256 + co) * 49];
#pragma unroll
    for (int p = 0; p < 49; p++) outp[p] = acc[p];
}

// wide chunk-sum + bias + relu: one thread per (b,co,pix) = 200704
__global__ void k_relu_sum(const float* __restrict__ conv_b) {
    int idx = blockIdx.x * 256 + threadIdx.x;
    if (idx < Bsz * CCONV * 49) {
        int pix = idx % 49;
        int co  = (idx / 49) & 255;
        int b   = idx / (49 * 256);
        float s = conv_b[co];
#pragma unroll
        for (int ch = 0; ch < NCH; ch++)
            s += g_part[(size_t)((b * NCH + ch) * 256 + co) * 49 + pix];
        g_hsum[idx] = fmaxf(s, 0.f);
    }
}

// mean over pixels + squash over channels
__global__ void k_squash_p() {
    int b = blockIdx.x;
    int co = threadIdx.x;
    const float* hp = &g_hsum[(b * 256 + co) * 49];
    float acc = 0.f;
#pragma unroll
    for (int pix = 0; pix < 49; pix++) acc += hp[pix];
    float p = acc * (1.f / 49.f);

    __shared__ float red[256];
    red[co] = p * p;
    __syncthreads();
    for (int st = 128; st > 0; st >>= 1) {
        if (co < st) red[co] += red[co + st];
        __syncthreads();
    }
    float msq = red[0];
    float sq = p * msq / ((1.f + msq) * sqrtf(msq));
    g_sq[b * 256 + co] = sq;
}

// ---------------- routing ----------------

__global__ void __launch_bounds__(256) k_route_sj() {
    int j = blockIdx.x;
    int t = threadIdx.x;
    __shared__ float cs[256];
    __shared__ float csq[16 * 256];
    __shared__ float ws[256 * 16];
    __shared__ float red[256];

    float bv = g_bij[j * 256 + t];
    red[t] = bv;
    __syncthreads();
    for (int st = 128; st > 0; st >>= 1) {
        if (t < st) red[t] = fmaxf(red[t], red[t + st]);
        __syncthreads();
    }
    float mx = red[0];
    __syncthreads();
    float e = expf(bv - mx);
    red[t] = e;
    __syncthreads();
    for (int st = 128; st > 0; st >>= 1) {
        if (t < st) red[t] += red[t + st];
        __syncthreads();
    }
    float denom = red[0];
    cs[t] = e / denom;
    for (int i = t; i < 256 * 16; i += 256) {
        int c = i >> 4, o = i & 15;
        ws[i] = g_Wsum[c * (NOUT * DOUT) + j * DOUT + o];
    }
    __syncthreads();
    for (int i = t; i < 16 * 256; i += 256)
        csq[i] = cs[i & 255] * g_sq[i];
    __syncthreads();

    int b = t >> 4, o = t & 15;
    const float* cq = &csq[b * 256];
    float acc = 0.f;
#pragma unroll 8
    for (int c = 0; c < 256; c++)
        acc = fmaf(cq[c], ws[c * 16 + o], acc);
    g_sj[(b * NOUT + j) * DOUT + o] = acc;
}

__global__ void k_route_v() {
    int b = blockIdx.x;
    int t = threadIdx.x;
    int o = t & 15, part = t >> 4;
    __shared__ float red[256];
    float s = 0.f;
    for (int j = part; j < NOUT; j += 16) {
        float v = g_sj[(b * NOUT + j) * DOUT + o];
        s += v * v;
    }
    red[t] = s;
    __syncthreads();
    for (int st = 128; st >= 16; st >>= 1) {
        if (t < st) red[t] += red[t + st];
        __syncthreads();
    }
    float msq = red[o];
    float scale = msq / ((1.f + msq) * sqrtf(msq));
    for (int j = part; j < NOUT; j += 16) {
        int i = (b * NOUT + j) * DOUT + o;
        g_v[i] = scale * g_sj[i];
    }
}

__global__ void k_route_update() {
    int j = blockIdx.x;
    int c = threadIdx.x;
    __shared__ float vs[16 * 16];
    if (c < 256) {
        int b = c >> 4, o = c & 15;
        vs[c] = g_v[(b * NOUT + j) * DOUT + o];
    }
    __syncthreads();
    const float4* w4 = (const float4*)&g_Wsum[(c * NOUT + j) * DOUT];
    float4 wa = w4[0], wb = w4[1], wc = w4[2], wd = w4[3];
    float w[16] = {wa.x, wa.y, wa.z, wa.w, wb.x, wb.y, wb.z, wb.w,
                   wc.x, wc.y, wc.z, wc.w, wd.x, wd.y, wd.z, wd.w};
    float q = 0.f;
#pragma unroll
    for (int b = 0; b < 16; b++) {
        float dot = 0.f;
#pragma unroll
        for (int o = 0; o < 16; o++) dot = fmaf(w[o], vs[b * 16 + o], dot);
        q = fmaf(g_sq[b * 256 + c], dot, q);
    }
    g_bij[j * 256 + c] += q * (1.f / 16.f);
}

__global__ void k_ba_f0(float* __restrict__ out) {
    int idx = blockIdx.x * 256 + threadIdx.x;   // 1648
    if (idx < Bsz * NOUT) {
        int b = idx / NOUT, j = idx % NOUT;
        const float* vp = &g_v[(b * NOUT + j) * DOUT];
        float msq = 0.f;
#pragma unroll
        for (int o = 0; o < 16; o++) msq = fmaf(vp[o], vp[o], msq);
        float ba = sqrtf(msq);
        out[b * NOUT + j] = ba;
        float* f0 = &g_f0[b * F0N + j * 16];
#pragma unroll
        for (int o = 0; o < 16; o++) f0[o] = vp[o] * ba;
    }
}

// ---------------- FC GEMM: cp.async double-buffered weight staging ----------------
// 2 cols/thread (TN=512 per block), 16 batches -> 16 u64 FMA2 accumulators.
// Stage = 8 K-rows of weights (16KB) + activations (512B); one stage in flight.
__global__ void __launch_bounds__(256) k_gemm_ca(int fin_sel,
                                                 const float* __restrict__ W,
                                                 int N, int K, int kchunk) {
    const float* fin = (fin_sel == 0) ? g_f0 : (fin_sel == 1) ? g_f1 : g_f2;
    __shared__ __align__(16) float ws[2][8][TN];
    __shared__ __align__(16) float fa[2][8][16];

    int tid = threadIdx.x;
    int s0 = blockIdx.y;
    int nbase = blockIdx.x * TN;
    int k0 = s0 * kchunk;
    int k1 = min(K, k0 + kchunk);
    int nst = (k1 - k0 + 7) >> 3;

    int n0 = nbase + tid, n1 = nbase + tid + 256;
    bool v0 = (n0 < N), v1 = (n1 < N);

    unsigned long long acc[16];
#pragma unroll
    for (int p = 0; p < 16; p++) acc[p] = 0ull;

    unsigned wsa = (unsigned)__cvta_generic_to_shared(&ws[0][0][0]);
    unsigned faa = (unsigned)__cvta_generic_to_shared(&fa[0][0][0]);

#define ISSUE_STAGE(S) do {                                               \
        int _s = (S);                                                     \
        int _buf = _s & 1;                                                \
        int _r0 = k0 + _s * 8;                                            \
        int _valid = k1 - _r0; if (_valid > 8) _valid = 8;                \
        _Pragma("unroll")                                                 \
        for (int _i = 0; _i < 16; _i++) {                                 \
            int _e = tid + _i * 256;                                      \
            int _r = _e >> 9, _col = _e & 511;                            \
            if (_r < _valid) {                                            \
                int _gc = nbase + _col; if (_gc >= N) _gc = N - 1;        \
                const float* _src = W + (size_t)(_r0 + _r) * N + _gc;     \
                unsigned _dst = wsa + (unsigned)(((_buf * 8 + _r) * TN + _col) * 4); \
                CP_ASYNC4(_dst, _src);                                    \
            }                                                             \
        }                                                                 \
        if (tid < 128) {                                                  \
            int _r = tid >> 4, _b = tid & 15;                             \
            if (_r < _valid) {                                            \
                const float* _src = fin + (size_t)_b * K + _r0 + _r;      \
                unsigned _dst = faa + (unsigned)(((_buf * 8 + _r) * 16 + _b) * 4); \
                CP_ASYNC4(_dst, _src);                                    \
            }                                                             \
        }                                                                 \
    } while (0)

    ISSUE_STAGE(0);
    CP_COMMIT();

    for (int s = 0; s < nst; s++) {
        if (s + 1 < nst) {
            ISSUE_STAGE(s + 1);
            CP_COMMIT();
            CP_WAIT1();
        } else {
            CP_WAIT0();
        }
        __syncthreads();

        int buf = s & 1;
        int kcnt = k1 - k0 - s * 8; if (kcnt > 8) kcnt = 8;
        if (kcnt == 8) {
#pragma unroll
            for (int kk = 0; kk < 8; kk++) {
                float w0 = ws[buf][kk][tid];
                float w1 = ws[buf][kk][tid + 256];
                unsigned long long p0, p1;
                PACK2(p0, w0); PACK2(p1, w1);
                const ulonglong2* f4 = (const ulonglong2*)&fa[buf][kk][0];
                ulonglong2 q0 = f4[0], q1 = f4[1], q2 = f4[2], q3 = f4[3];
                FMA_F32X2(acc[0],  p0, q0.x); FMA_F32X2(acc[1],  p0, q0.y);
                FMA_F32X2(acc[2],  p0, q1.x); FMA_F32X2(acc[3],  p0, q1.y);
                FMA_F32X2(acc[4],  p0, q2.x); FMA_F32X2(acc[5],  p0, q2.y);
                FMA_F32X2(acc[6],  p0, q3.x); FMA_F32X2(acc[7],  p0, q3.y);
                FMA_F32X2(acc[8],  p1, q0.x); FMA_F32X2(acc[9],  p1, q0.y);
                FMA_F32X2(acc[10], p1, q1.x); FMA_F32X2(acc[11], p1, q1.y);
                FMA_F32X2(acc[12], p1, q2.x); FMA_F32X2(acc[13], p1, q2.y);
                FMA_F32X2(acc[14], p1, q3.x); FMA_F32X2(acc[15], p1, q3.y);
            }
        } else {
            for (int kk = 0; kk < kcnt; kk++) {
                float w0 = ws[buf][kk][tid];
                float w1 = ws[buf][kk][tid + 256];
                unsigned long long p0, p1;
                PACK2(p0, w0); PACK2(p1, w1);
                const ulonglong2* f4 = (const ulonglong2*)&fa[buf][kk][0];
                ulonglong2 q0 = f4[0], q1 = f4[1], q2 = f4[2], q3 = f4[3];
                FMA_F32X2(acc[0],  p0, q0.x); FMA_F32X2(acc[1],  p0, q0.y);
                FMA_F32X2(acc[2],  p0, q1.x); FMA_F32X2(acc[3],  p0, q1.y);
                FMA_F32X2(acc[4],  p0, q2.x); FMA_F32X2(acc[5],  p0, q2.y);
                FMA_F32X2(acc[6],  p0, q3.x); FMA_F32X2(acc[7],  p0, q3.y);
                FMA_F32X2(acc[8],  p1, q0.x); FMA_F32X2(acc[9],  p1, q0.y);
                FMA_F32X2(acc[10], p1, q1.x); FMA_F32X2(acc[11], p1, q1.y);
                FMA_F32X2(acc[12], p1, q2.x); FMA_F32X2(acc[13], p1, q2.y);
                FMA_F32X2(acc[14], p1, q3.x); FMA_F32X2(acc[15], p1, q3.y);
            }
        }
        __syncthreads();
    }
#undef ISSUE_STAGE

    if (v0) {
#pragma unroll
        for (int p = 0; p < 8; p++) {
            unsigned long long a = acc[p];
            g_fcpart[(size_t)(s0 * 16 + 2 * p + 0) * N + n0] = __uint_as_float((unsigned int)a);
            g_fcpart[(size_t)(s0 * 16 + 2 * p + 1) * N + n0] = __uint_as_float((unsigned int)(a >> 32));
        }
    }
    if (v1) {
#pragma unroll
        for (int p = 0; p < 8; p++) {
            unsigned long long a = acc[8 + p];
            g_fcpart[(size_t)(s0 * 16 + 2 * p + 0) * N + n1] = __uint_as_float((unsigned int)a);
            g_fcpart[(size_t)(s0 * 16 + 2 * p + 1) * N + n1] = __uint_as_float((unsigned int)(a >> 32));
        }
    }
}

// deterministic k-split reduction + bias.
// out_sel: 0 -> g_f1, 1 -> g_f2, 2 -> harness out pointer (recon region)
__global__ void k_reduce(const float* __restrict__ bias,
                         int N, int S, int out_sel, float* __restrict__ hout) {
    float* out = (out_sel == 0) ? g_f1 : (out_sel == 1) ? g_f2 : hout;
    int idx = blockIdx.x * 256 + threadIdx.x;
    if (idx < 16 * N) {
        int b = idx / N, n = idx - b * N;
        float s = bias[n];
        for (int sp = 0; sp < S; sp++) s += g_fcpart[(size_t)(sp * 16 + b) * N + n];
        out[b * N + n] = s;
    }
}

// ---------------- launcher ----------------
extern "C" void kernel_launch(void* const* d_in, const int* in_sizes, int n_in,
                              void* d_out, int out_size) {
    const float* x      = (const float*)d_in[0];
    const float* conv_w = (const float*)d_in[1];
    const float* conv_b = (const float*)d_in[2];
    const float* W_caps = (const float*)d_in[3];
    const float* fc1_w  = (const float*)d_in[4];
    const float* fc1_b  = (const float*)d_in[5];
    const float* fc2_w  = (const float*)d_in[6];
    const float* fc2_b  = (const float*)d_in[7];
    const float* fc3_w  = (const float*)d_in[8];
    const float* fc3_b  = (const float*)d_in[9];
    float* out = (float*)d_out;

    (void)in_sizes; (void)n_in; (void)out_size;

    k_prep<<<(927 * 256 + NOUT * CCONV + 255) / 256, 256>>>(conv_w);
    k_wsum<<<1648, 256>>>(W_caps);
    k_conv<<<dim3(NCH, 16), 256>>>(x);
    k_relu_sum<<<(Bsz * CCONV * 49 + 255) / 256, 256>>>(conv_b);
    k_squash_p<<<16, 256>>>();

    for (int it = 0; it < 3; it++) {
        k_route_sj<<<103, 256>>>();
        k_route_v<<<16, 256>>>();
        if (it < 2) k_route_update<<<103, 256>>>();
    }
    k_ba_f0<<<7, 256>>>(out);

    // fc1: (16x1648)@(1648x5562)   tiles=11, S=24 (chunk 69)  -> 264 blocks, 2.13M partials
    k_gemm_ca<<<dim3(11, 24), 256>>>(0, fc1_w, H1N, F0N, 69);
    k_reduce<<<(16 * H1N + 255) / 256, 256>>>(fc1_b, H1N, 24, 0, out);
    // fc2: (16x5562)@(5562x12514)  tiles=25, S=24 (chunk 232) -> 600 blocks, 4.81M partials
    k_gemm_ca<<<dim3(25, 24), 256>>>(1, fc2_w, H2N, H1N, 232);
    k_reduce<<<(16 * H2N + 255) / 256, 256>>>(fc2_b, H2N, 24, 1, out);
    // fc3: (16x12514)@(12514x8343) tiles=17, S=24 (chunk 522) -> 408 blocks, 3.20M partials
    k_gemm_ca<<<dim3(17, 24), 256>>>(2, fc3_w, RECN, H2N, 522);
    k_reduce<<<(16 * RECN + 255) / 256, 256>>>(fc3_b, RECN, 24, 2, out + Bsz * NOUT);
}

// round 14
// speedup vs baseline: 1.5832x; 1.5832x over previous
#include <cuda_runtime.h>
#include <math.h>

// ---------------- problem constants ----------------
#define Bsz    16
#define CIN    103
#define CCONV  256
#define NOUT   103
#define DOUT   16
#define RECN   8343            // 9*9*103 (odd!)
#define H1N    5562            // even
#define H2N    12514           // even
#define F0N    1648            // NOUT*DOUT
#define NCH    15              // conv ci-chunks (7 channels each)

// ---------------- scratch (device globals; no allocation) ----------------
__device__ float g_wT[927 * 256];              // transposed conv weights [e=ci*9+k][co]
__device__ float g_Wsum[CCONV * NOUT * DOUT];  // sum over prim axis of W_caps
__device__ float g_part[Bsz * NCH * CCONV * 49];
__device__ float g_hsum[Bsz * CCONV * 49];     // relu'd conv activations
__device__ float g_sq[Bsz * CCONV];
__device__ float g_bij[NOUT * CCONV];
__device__ float g_sj[Bsz * NOUT * DOUT];
__device__ float g_v[Bsz * NOUT * DOUT];
__device__ float g_f0[Bsz * F0N];
__device__ float g_f1[Bsz * H1N];
__device__ float g_f2[Bsz * H2N];
// max partials: fc2 23*16*12514 = 4,605,152
__device__ float g_fcpart[23 * Bsz * H2N + 64];

// packed f32x2 FMA (sm_103a FFMA2 — PTX-only, ptxas never auto-fuses)
#define FMA_F32X2(acc, a, b) \
    asm("fma.rn.f32x2 %0, %1, %2, %0;" : "+l"(acc) : "l"(a), "l"(b))
#define PACK2(dst, w) \
    asm("mov.b64 %0, {%1, %1};" : "=l"(dst) : "f"(w))

// ---------------- small prep kernels ----------------

// conv-weight transpose + routing-logit init fused
__global__ void k_prep(const float* __restrict__ w) {
    int idx = blockIdx.x * 256 + threadIdx.x;
    if (idx < 927 * 256) {
        int e = idx >> 8, co = idx & 255;
        g_wT[idx] = w[co * 927 + e];
    } else {
        int r = idx - 927 * 256;
        if (r < NOUT * CCONV) g_bij[r] = 1.0f;
    }
}

__global__ void k_wsum(const float* __restrict__ Wc) {
    int idx = blockIdx.x * 256 + threadIdx.x;        // 256*103*16
    if (idx < CCONV * NOUT * DOUT) {
        const float4* p = (const float4*)(Wc + (size_t)idx * 32);
        float s = 0.f;
#pragma unroll
        for (int i = 0; i < 8; i++) {
            float4 v = p[i];
            s += v.x + v.y + v.z + v.w;
        }
        g_Wsum[idx] = s;
    }
}

// ---------------- conv (single kernel, weight double-buffer) ----------------
__global__ void __launch_bounds__(256) k_conv(const float* __restrict__ x) {
    int chunk = blockIdx.x, b = blockIdx.y;
    int ci0 = chunk * 7;
    int cnt = min(7, CIN - ci0);
    __shared__ float xs[7 * 81];
    const float* xp = x + (b * CIN + ci0) * 81;
    for (int i = threadIdx.x; i < cnt * 81; i += 256) xs[i] = xp[i];
    __syncthreads();

    int co = threadIdx.x;
    float acc[49];
#pragma unroll
    for (int p = 0; p < 49; p++) acc[p] = 0.f;

    float wA[9], wB[9];
#pragma unroll
    for (int k = 0; k < 9; k++) wA[k] = g_wT[(ci0 * 9 + k) * 256 + co];

    for (int cl = 0; cl < cnt; cl++) {
        if (cl + 1 < cnt) {
#pragma unroll
            for (int k = 0; k < 9; k++)
                wB[k] = g_wT[((ci0 + cl + 1) * 9 + k) * 256 + co];
        }
        const float* xr0 = &xs[cl * 81];
#pragma unroll
        for (int r = 0; r < 9; r++) {
            float xr[9];
#pragma unroll
            for (int q = 0; q < 9; q++) xr[q] = xr0[r * 9 + q];
#pragma unroll
            for (int kh = 0; kh < 3; kh++) {
                int ph = r - kh;
                if (ph >= 0 && ph < 7) {
#pragma unroll
                    for (int pw = 0; pw < 7; pw++) {
#pragma unroll
                        for (int kw = 0; kw < 3; kw++)
                            acc[ph * 7 + pw] = fmaf(wA[kh * 3 + kw], xr[pw + kw], acc[ph * 7 + pw]);
                    }
                }
            }
        }
#pragma unroll
        for (int k = 0; k < 9; k++) wA[k] = wB[k];
    }
    float* outp = &g_part[((b * NCH + chunk) * 256 + co) * 49];
#pragma unroll
    for (int p = 0; p < 49; p++) outp[p] = acc[p];
}

// wide chunk-sum + bias + relu: one thread per (b,co,pix) = 200704
__global__ void k_relu_sum(const float* __restrict__ conv_b) {
    int idx = blockIdx.x * 256 + threadIdx.x;
    if (idx < Bsz * CCONV * 49) {
        int pix = idx % 49;
        int co  = (idx / 49) & 255;
        int b   = idx / (49 * 256);
        float s = conv_b[co];
#pragma unroll
        for (int ch = 0; ch < NCH; ch++)
            s += g_part[(size_t)((b * NCH + ch) * 256 + co) * 49 + pix];
        g_hsum[idx] = fmaxf(s, 0.f);
    }
}

// mean over pixels + squash over channels
__global__ void k_squash_p() {
    int b = blockIdx.x;
    int co = threadIdx.x;
    const float* hp = &g_hsum[(b * 256 + co) * 49];
    float acc = 0.f;
#pragma unroll
    for (int pix = 0; pix < 49; pix++) acc += hp[pix];
    float p = acc * (1.f / 49.f);

    __shared__ float red[256];
    red[co] = p * p;
    __syncthreads();
    for (int st = 128; st > 0; st >>= 1) {
        if (co < st) red[co] += red[co + st];
        __syncthreads();
    }
    float msq = red[0];
    float sq = p * msq / ((1.f + msq) * sqrtf(msq));
    g_sq[b * 256 + co] = sq;
}

// ---------------- routing ----------------

__global__ void __launch_bounds__(256) k_route_sj() {
    int j = blockIdx.x;
    int t = threadIdx.x;
    __shared__ float cs[256];
    __shared__ float csq[16 * 256];
    __shared__ float ws[256 * 16];
    __shared__ float red[256];

    float bv = g_bij[j * 256 + t];
    red[t] = bv;
    __syncthreads();
    for (int st = 128; st > 0; st >>= 1) {
        if (t < st) red[t] = fmaxf(red[t], red[t + st]);
        __syncthreads();
    }
    float mx = red[0];
    __syncthreads();
    float e = expf(bv - mx);
    red[t] = e;
    __syncthreads();
    for (int st = 128; st > 0; st >>= 1) {
        if (t < st) red[t] += red[t + st];
        __syncthreads();
    }
    float denom = red[0];
    cs[t] = e / denom;
    for (int i = t; i < 256 * 16; i += 256) {
        int c = i >> 4, o = i & 15;
        ws[i] = g_Wsum[c * (NOUT * DOUT) + j * DOUT + o];
    }
    __syncthreads();
    for (int i = t; i < 16 * 256; i += 256)
        csq[i] = cs[i & 255] * g_sq[i];
    __syncthreads();

    int b = t >> 4, o = t & 15;
    const float* cq = &csq[b * 256];
    float acc = 0.f;
#pragma unroll 8
    for (int c = 0; c < 256; c++)
        acc = fmaf(cq[c], ws[c * 16 + o], acc);
    g_sj[(b * NOUT + j) * DOUT + o] = acc;
}

__global__ void k_route_v() {
    int b = blockIdx.x;
    int t = threadIdx.x;
    int o = t & 15, part = t >> 4;
    __shared__ float red[256];
    float s = 0.f;
    for (int j = part; j < NOUT; j += 16) {
        float v = g_sj[(b * NOUT + j) * DOUT + o];
        s += v * v;
    }
    red[t] = s;
    __syncthreads();
    for (int st = 128; st >= 16; st >>= 1) {
        if (t < st) red[t] += red[t + st];
        __syncthreads();
    }
    float msq = red[o];
    float scale = msq / ((1.f + msq) * sqrtf(msq));
    for (int j = part; j < NOUT; j += 16) {
        int i = (b * NOUT + j) * DOUT + o;
        g_v[i] = scale * g_sj[i];
    }
}

__global__ void k_route_update() {
    int j = blockIdx.x;
    int c = threadIdx.x;
    __shared__ float vs[16 * 16];
    if (c < 256) {
        int b = c >> 4, o = c & 15;
        vs[c] = g_v[(b * NOUT + j) * DOUT + o];
    }
    __syncthreads();
    const float4* w4 = (const float4*)&g_Wsum[(c * NOUT + j) * DOUT];
    float4 wa = w4[0], wb = w4[1], wc = w4[2], wd = w4[3];
    float w[16] = {wa.x, wa.y, wa.z, wa.w, wb.x, wb.y, wb.z, wb.w,
                   wc.x, wc.y, wc.z, wc.w, wd.x, wd.y, wd.z, wd.w};
    float q = 0.f;
#pragma unroll
    for (int b = 0; b < 16; b++) {
        float dot = 0.f;
#pragma unroll
        for (int o = 0; o < 16; o++) dot = fmaf(w[o], vs[b * 16 + o], dot);
        q = fmaf(g_sq[b * 256 + c], dot, q);
    }
    g_bij[j * 256 + c] += q * (1.f / 16.f);
}

__global__ void k_ba_f0(float* __restrict__ out) {
    int idx = blockIdx.x * 256 + threadIdx.x;   // 1648
    if (idx < Bsz * NOUT) {
        int b = idx / NOUT, j = idx % NOUT;
        const float* vp = &g_v[(b * NOUT + j) * DOUT];
        float msq = 0.f;
#pragma unroll
        for (int o = 0; o < 16; o++) msq = fmaf(vp[o], vp[o], msq);
        float ba = sqrtf(msq);
        out[b * NOUT + j] = ba;
        float* f0 = &g_f0[b * F0N + j * 16];
#pragma unroll
        for (int o = 0; o < 16; o++) f0[o] = vp[o] * ba;
    }
}

// ---------------- FC GEMM (scalar, R7 version — used for fc3, odd N) ----------------
// 4 columns per thread (stride 256), 16 batches -> 32 u64 FMA2 accumulators.
__global__ void __launch_bounds__(256, 2) k_gemm4(int fin_sel,
                                                  const float* __restrict__ W,
                                                  int N, int K, int kchunk) {
    const float* fin = (fin_sel == 0) ? g_f0 : (fin_sel == 1) ? g_f1 : g_f2;
    int s = blockIdx.y;
    int nb = blockIdx.x * 1024 + threadIdx.x;
    int k0 = s * kchunk;
    int k1 = min(K, k0 + kchunk);

    int nc[4];
    bool vld[4];
#pragma unroll
    for (int c = 0; c < 4; c++) {
        int n = nb + c * 256;
        vld[c] = (n < N);
        nc[c] = vld[c] ? n : 0;
    }

    __shared__ __align__(16) float fs[128 * 16];   // [kk][b]
    unsigned long long acc[32];
#pragma unroll
    for (int p = 0; p < 32; p++) acc[p] = 0ull;

    for (int kt = k0; kt < k1; kt += 128) {
        int kc = min(128, k1 - kt);
        __syncthreads();
        for (int i = threadIdx.x; i < 16 * 128; i += 256) {
            int b = i >> 7, kk = i & 127;
            if (kk < kc) fs[kk * 16 + b] = fin[b * K + kt + kk];
        }
        __syncthreads();

        const float* wp = W + (size_t)kt * N;
#pragma unroll 4
        for (int kk = 0; kk < kc; kk++) {
            const float* wr = wp + (size_t)kk * N;
            float w0 = wr[nc[0]], w1 = wr[nc[1]], w2 = wr[nc[2]], w3 = wr[nc[3]];
            unsigned long long p0, p1, p2, p3;
            PACK2(p0, w0); PACK2(p1, w1); PACK2(p2, w2); PACK2(p3, w3);
            const unsigned long long* f2 = (const unsigned long long*)&fs[kk * 16];
#pragma unroll
            for (int p = 0; p < 8; p++) {
                unsigned long long fv = f2[p];
                FMA_F32X2(acc[p],      p0, fv);
                FMA_F32X2(acc[8 + p],  p1, fv);
                FMA_F32X2(acc[16 + p], p2, fv);
                FMA_F32X2(acc[24 + p], p3, fv);
            }
        }
    }

#pragma unroll
    for (int c = 0; c < 4; c++) {
        if (vld[c]) {
#pragma unroll
            for (int p = 0; p < 8; p++) {
                unsigned long long a = acc[c * 8 + p];
                float lo = __uint_as_float((unsigned int)a);
                float hi = __uint_as_float((unsigned int)(a >> 32));
                g_fcpart[(size_t)(s * 16 + 2 * p + 0) * N + nc[c]] = lo;
                g_fcpart[(size_t)(s * 16 + 2 * p + 1) * N + nc[c]] = hi;
            }
        }
    }
}

// ---------------- FC GEMM (vectorized, N even — fc1/fc2) ----------------
// 2 adjacent-column pairs per thread: cols (2t,2t+1) and (512+2t,513+2t).
// Weight loads are LDG.64 (8B-aligned because N even), stores STG.64.
__global__ void __launch_bounds__(256, 2) k_gemm2v(int fin_sel,
                                                   const float* __restrict__ W,
                                                   int N, int K, int kchunk) {
    const float* fin = (fin_sel == 0) ? g_f0 : (fin_sel == 1) ? g_f1 : g_f2;
    int s = blockIdx.y;
    int t = threadIdx.x;
    int nbase = blockIdx.x * 1024;
    int k0 = s * kchunk;
    int k1 = min(K, k0 + kchunk);

    int c0 = nbase + 2 * t;          // even
    int c1 = nbase + 512 + 2 * t;    // even
    bool v0 = (c0 < N), v1 = (c1 < N);   // N even: c0<N implies c0+1<N
    int p0i = v0 ? c0 : 0;            // clamped even -> 8B aligned
    int p1i = v1 ? c1 : 0;

    __shared__ __align__(16) float fs[128 * 16];   // [kk][b]
    unsigned long long acc[32];
#pragma unroll
    for (int p = 0; p < 32; p++) acc[p] = 0ull;

    for (int kt = k0; kt < k1; kt += 128) {
        int kc = min(128, k1 - kt);
        __syncthreads();
        for (int i = threadIdx.x; i < 16 * 128; i += 256) {
            int b = i >> 7, kk = i & 127;
            if (kk < kc) fs[kk * 16 + b] = fin[b * K + kt + kk];
        }
        __syncthreads();

        const float* wp = W + (size_t)kt * N;
#pragma unroll 4
        for (int kk = 0; kk < kc; kk++) {
            const float* wr = wp + (size_t)kk * N;
            float2 wa = *(const float2*)(wr + p0i);
            float2 wb = *(const float2*)(wr + p1i);
            unsigned long long q0, q1, q2, q3;
            PACK2(q0, wa.x); PACK2(q1, wa.y); PACK2(q2, wb.x); PACK2(q3, wb.y);
            const unsigned long long* f2 = (const unsigned long long*)&fs[kk * 16];
#pragma unroll
            for (int p = 0; p < 8; p++) {
                unsigned long long fv = f2[p];
                FMA_F32X2(acc[p],      q0, fv);   // col c0
                FMA_F32X2(acc[8 + p],  q1, fv);   // col c0+1
                FMA_F32X2(acc[16 + p], q2, fv);   // col c1
                FMA_F32X2(acc[24 + p], q3, fv);   // col c1+1
            }
        }
    }

    // stores: float2 per (row, col-pair)
    if (v0) {
#pragma unroll
        for (int p = 0; p < 8; p++) {
            unsigned long long aL = acc[p], aH = acc[8 + p];
            float2 e, o2;
            e.x  = __uint_as_float((unsigned int)aL);
            e.y  = __uint_as_float((unsigned int)aH);
            o2.x = __uint_as_float((unsigned int)(aL >> 32));
            o2.y = __uint_as_float((unsigned int)(aH >> 32));
            *(float2*)&g_fcpart[(size_t)(s * 16 + 2 * p + 0) * N + c0] = e;
            *(float2*)&g_fcpart[(size_t)(s * 16 + 2 * p + 1) * N + c0] = o2;
        }
    }
    if (v1) {
#pragma unroll
        for (int p = 0; p < 8; p++) {
            unsigned long long aL = acc[16 + p], aH = acc[24 + p];
            float2 e, o2;
            e.x  = __uint_as_float((unsigned int)aL);
            e.y  = __uint_as_float((unsigned int)aH);
            o2.x = __uint_as_float((unsigned int)(aL >> 32));
            o2.y = __uint_as_float((unsigned int)(aH >> 32));
            *(float2*)&g_fcpart[(size_t)(s * 16 + 2 * p + 0) * N + c1] = e;
            *(float2*)&g_fcpart[(size_t)(s * 16 + 2 * p + 1) * N + c1] = o2;
        }
    }
}

// deterministic k-split reduction + bias.
// out_sel: 0 -> g_f1, 1 -> g_f2, 2 -> harness out pointer (recon region)
__global__ void k_reduce(const float* __restrict__ bias,
                         int N, int S, int out_sel, float* __restrict__ hout) {
    float* out = (out_sel == 0) ? g_f1 : (out_sel == 1) ? g_f2 : hout;
    int idx = blockIdx.x * 256 + threadIdx.x;
    if (idx < 16 * N) {
        int b = idx / N, n = idx - b * N;
        float s = bias[n];
        for (int sp = 0; sp < S; sp++) s += g_fcpart[(size_t)(sp * 16 + b) * N + n];
        out[b * N + n] = s;
    }
}

// ---------------- launcher ----------------
extern "C" void kernel_launch(void* const* d_in, const int* in_sizes, int n_in,
                              void* d_out, int out_size) {
    const float* x      = (const float*)d_in[0];
    const float* conv_w = (const float*)d_in[1];
    const float* conv_b = (const float*)d_in[2];
    const float* W_caps = (const float*)d_in[3];
    const float* fc1_w  = (const float*)d_in[4];
    const float* fc1_b  = (const float*)d_in[5];
    const float* fc2_w  = (const float*)d_in[6];
    const float* fc2_b  = (const float*)d_in[7];
    const float* fc3_w  = (const float*)d_in[8];
    const float* fc3_b  = (const float*)d_in[9];
    float* out = (float*)d_out;

    (void)in_sizes; (void)n_in; (void)out_size;

    k_prep<<<(927 * 256 + NOUT * CCONV + 255) / 256, 256>>>(conv_w);
    k_wsum<<<1648, 256>>>(W_caps);
    k_conv<<<dim3(NCH, 16), 256>>>(x);
    k_relu_sum<<<(Bsz * CCONV * 49 + 255) / 256, 256>>>(conv_b);
    k_squash_p<<<16, 256>>>();

    for (int it = 0; it < 3; it++) {
        k_route_sj<<<103, 256>>>();
        k_route_v<<<16, 256>>>();
        if (it < 2) k_route_update<<<103, 256>>>();
    }
    k_ba_f0<<<7, 256>>>(out);

    // fc1: (16x1648)@(1648x5562)   tiles=6,  S=26 (chunk 64)  -> 156 blocks  [vector]
    k_gemm2v<<<dim3(6, 26), 256>>>(0, fc1_w, H1N, F0N, 64);
    k_reduce<<<(16 * H1N + 255) / 256, 256>>>(fc1_b, H1N, 26, 0, out);
    // fc2: (16x5562)@(5562x12514)  tiles=13, S=23 (chunk 242) -> 299 blocks  [vector]
    k_gemm2v<<<dim3(13, 23), 256>>>(1, fc2_w, H2N, H1N, 242);
    k_reduce<<<(16 * H2N + 255) / 256, 256>>>(fc2_b, H2N, 23, 1, out);
    // fc3: (16x12514)@(12514x8343) tiles=9,  S=33 (chunk 380) -> 297 blocks  [scalar, N odd]
    k_gemm4<<<dim3(9, 33), 256>>>(2, fc3_w, RECN, H2N, 380);
    k_reduce<<<(16 * RECN + 255) / 256, 256>>>(fc3_b, RECN, 33, 2, out + Bsz * NOUT);
}

// round 17
// speedup vs baseline: 1.6340x; 1.0321x over previous
#include <cuda_runtime.h>
#include <math.h>

// ---------------- problem constants ----------------
#define Bsz    16
#define CIN    103
#define CCONV  256
#define NOUT   103
#define DOUT   16
#define RECN   8343            // 9*9*103 (odd!)
#define H1N    5562            // even
#define H2N    12514           // even
#define F0N    1648            // NOUT*DOUT
#define NCH    15              // conv ci-chunks (7 channels each)

// ---------------- scratch (device globals; no allocation) ----------------
__device__ float g_wT[927 * 256];              // transposed conv weights [e=ci*9+k][co]
__device__ float g_Wsum[CCONV * NOUT * DOUT];  // sum over prim axis of W_caps
__device__ float g_part[Bsz * NCH * CCONV * 49];
__device__ float g_hsum[Bsz * CCONV * 49];     // relu'd conv activations
__device__ float g_sq[Bsz * CCONV];
__device__ float g_bij[NOUT * CCONV];
__device__ float g_sj[Bsz * NOUT * DOUT];
__device__ float g_v[Bsz * NOUT * DOUT];
__device__ float g_f0[Bsz * F0N];
__device__ float g_f1[Bsz * H1N];
__device__ float g_f2[Bsz * H2N];
// max partials: fc2 23*16*12514 = 4,605,152
__device__ float g_fcpart[23 * Bsz * H2N + 64];

// packed f32x2 FMA (sm_103a FFMA2 — PTX-only, ptxas never auto-fuses)
#define FMA_F32X2(acc, a, b) \
    asm("fma.rn.f32x2 %0, %1, %2, %0;" : "+l"(acc) : "l"(a), "l"(b))
#define PACK2(dst, w) \
    asm("mov.b64 %0, {%1, %1};" : "=l"(dst) : "f"(w))

// ---------------- small prep kernels ----------------

// conv-weight transpose + routing-logit init fused
__global__ void k_prep(const float* __restrict__ w) {
    int idx = blockIdx.x * 256 + threadIdx.x;
    if (idx < 927 * 256) {
        int e = idx >> 8, co = idx & 255;
        g_wT[idx] = w[co * 927 + e];
    } else {
        int r = idx - 927 * 256;
        if (r < NOUT * CCONV) g_bij[r] = 1.0f;
    }
}

__global__ void k_wsum(const float* __restrict__ Wc) {
    int idx = blockIdx.x * 256 + threadIdx.x;        // 256*103*16
    if (idx < CCONV * NOUT * DOUT) {
        const float4* p = (const float4*)(Wc + (size_t)idx * 32);
        float s = 0.f;
#pragma unroll
        for (int i = 0; i < 8; i++) {
            float4 v = p[i];
            s += v.x + v.y + v.z + v.w;
        }
        g_Wsum[idx] = s;
    }
}

// ---------------- conv (single kernel, weight double-buffer) ----------------
__global__ void __launch_bounds__(256) k_conv(const float* __restrict__ x) {
    int chunk = blockIdx.x, b = blockIdx.y;
    int ci0 = chunk * 7;
    int cnt = min(7, CIN - ci0);
    __shared__ float xs[7 * 81];
    const float* xp = x + (b * CIN + ci0) * 81;
    for (int i = threadIdx.x; i < cnt * 81; i += 256) xs[i] = xp[i];
    __syncthreads();

    int co = threadIdx.x;
    float acc[49];
#pragma unroll
    for (int p = 0; p < 49; p++) acc[p] = 0.f;

    float wA[9], wB[9];
#pragma unroll
    for (int k = 0; k < 9; k++) wA[k] = g_wT[(ci0 * 9 + k) * 256 + co];

    for (int cl = 0; cl < cnt; cl++) {
        if (cl + 1 < cnt) {
#pragma unroll
            for (int k = 0; k < 9; k++)
                wB[k] = g_wT[((ci0 + cl + 1) * 9 + k) * 256 + co];
        }
        const float* xr0 = &xs[cl * 81];
#pragma unroll
        for (int r = 0; r < 9; r++) {
            float xr[9];
#pragma unroll
            for (int q = 0; q < 9; q++) xr[q] = xr0[r * 9 + q];
#pragma unroll
            for (int kh = 0; kh < 3; kh++) {
                int ph = r - kh;
                if (ph >= 0 && ph < 7) {
#pragma unroll
                    for (int pw = 0; pw < 7; pw++) {
#pragma unroll
                        for (int kw = 0; kw < 3; kw++)
                            acc[ph * 7 + pw] = fmaf(wA[kh * 3 + kw], xr[pw + kw], acc[ph * 7 + pw]);
                    }
                }
            }
        }
#pragma unroll
        for (int k = 0; k < 9; k++) wA[k] = wB[k];
    }
    float* outp = &g_part[((b * NCH + chunk) * 256 + co) * 49];
#pragma unroll
    for (int p = 0; p < 49; p++) outp[p] = acc[p];
}

// wide chunk-sum + bias + relu: one thread per (b,co,pix) = 200704
__global__ void k_relu_sum(const float* __restrict__ conv_b) {
    int idx = blockIdx.x * 256 + threadIdx.x;
    if (idx < Bsz * CCONV * 49) {
        int pix = idx % 49;
        int co  = (idx / 49) & 255;
        int b   = idx / (49 * 256);
        float s = conv_b[co];
#pragma unroll
        for (int ch = 0; ch < NCH; ch++)
            s += g_part[(size_t)((b * NCH + ch) * 256 + co) * 49 + pix];
        g_hsum[idx] = fmaxf(s, 0.f);
    }
}

// mean over pixels + squash over channels
__global__ void k_squash_p() {
    int b = blockIdx.x;
    int co = threadIdx.x;
    const float* hp = &g_hsum[(b * 256 + co) * 49];
    float acc = 0.f;
#pragma unroll
    for (int pix = 0; pix < 49; pix++) acc += hp[pix];
    float p = acc * (1.f / 49.f);

    __shared__ float red[256];
    red[co] = p * p;
    __syncthreads();
    for (int st = 128; st > 0; st >>= 1) {
        if (co < st) red[co] += red[co + st];
        __syncthreads();
    }
    float msq = red[0];
    float sq = p * msq / ((1.f + msq) * sqrtf(msq));
    g_sq[b * 256 + co] = sq;
}

// ---------------- routing ----------------

__global__ void __launch_bounds__(256) k_route_sj() {
    int j = blockIdx.x;
    int t = threadIdx.x;
    __shared__ float cs[256];
    __shared__ float csq[16 * 256];
    __shared__ float ws[256 * 16];
    __shared__ float red[256];

    float bv = g_bij[j * 256 + t];
    red[t] = bv;
    __syncthreads();
    for (int st = 128; st > 0; st >>= 1) {
        if (t < st) red[t] = fmaxf(red[t], red[t + st]);
        __syncthreads();
    }
    float mx = red[0];
    __syncthreads();
    float e = expf(bv - mx);
    red[t] = e;
    __syncthreads();
    for (int st = 128; st > 0; st >>= 1) {
        if (t < st) red[t] += red[t + st];
        __syncthreads();
    }
    float denom = red[0];
    cs[t] = e / denom;
    for (int i = t; i < 256 * 16; i += 256) {
        int c = i >> 4, o = i & 15;
        ws[i] = g_Wsum[c * (NOUT * DOUT) + j * DOUT + o];
    }
    __syncthreads();
    for (int i = t; i < 16 * 256; i += 256)
        csq[i] = cs[i & 255] * g_sq[i];
    __syncthreads();

    int b = t >> 4, o = t & 15;
    const float* cq = &csq[b * 256];
    float acc = 0.f;
#pragma unroll 8
    for (int c = 0; c < 256; c++)
        acc = fmaf(cq[c], ws[c * 16 + o], acc);
    g_sj[(b * NOUT + j) * DOUT + o] = acc;
}

__global__ void k_route_v() {
    int b = blockIdx.x;
    int t = threadIdx.x;
    int o = t & 15, part = t >> 4;
    __shared__ float red[256];
    float s = 0.f;
    for (int j = part; j < NOUT; j += 16) {
        float v = g_sj[(b * NOUT + j) * DOUT + o];
        s += v * v;
    }
    red[t] = s;
    __syncthreads();
    for (int st = 128; st >= 16; st >>= 1) {
        if (t < st) red[t] += red[t + st];
        __syncthreads();
    }
    float msq = red[o];
    float scale = msq / ((1.f + msq) * sqrtf(msq));
    for (int j = part; j < NOUT; j += 16) {
        int i = (b * NOUT + j) * DOUT + o;
        g_v[i] = scale * g_sj[i];
    }
}

__global__ void k_route_update() {
    int j = blockIdx.x;
    int c = threadIdx.x;
    __shared__ float vs[16 * 16];
    if (c < 256) {
        int b = c >> 4, o = c & 15;
        vs[c] = g_v[(b * NOUT + j) * DOUT + o];
    }
    __syncthreads();
    const float4* w4 = (const float4*)&g_Wsum[(c * NOUT + j) * DOUT];
    float4 wa = w4[0], wb = w4[1], wc = w4[2], wd = w4[3];
    float w[16] = {wa.x, wa.y, wa.z, wa.w, wb.x, wb.y, wb.z, wb.w,
                   wc.x, wc.y, wc.z, wc.w, wd.x, wd.y, wd.z, wd.w};
    float q = 0.f;
#pragma unroll
    for (int b = 0; b < 16; b++) {
        float dot = 0.f;
#pragma unroll
        for (int o = 0; o < 16; o++) dot = fmaf(w[o], vs[b * 16 + o], dot);
        q = fmaf(g_sq[b * 256 + c], dot, q);
    }
    g_bij[j * 256 + c] += q * (1.f / 16.f);
}

__global__ void k_ba_f0(float* __restrict__ out) {
    int idx = blockIdx.x * 256 + threadIdx.x;   // 1648
    if (idx < Bsz * NOUT) {
        int b = idx / NOUT, j = idx % NOUT;
        const float* vp = &g_v[(b * NOUT + j) * DOUT];
        float msq = 0.f;
#pragma unroll
        for (int o = 0; o < 16; o++) msq = fmaf(vp[o], vp[o], msq);
        float ba = sqrtf(msq);
        out[b * NOUT + j] = ba;
        float* f0 = &g_f0[b * F0N + j * 16];
#pragma unroll
        for (int o = 0; o < 16; o++) f0[o] = vp[o] * ba;
    }
}

// ---------------- FC GEMM (even N: fc1/fc2) ----------------
// 2 adjacent cols per thread (one LDG.64/kk), 16 batches -> 16 u64 accs.
// __launch_bounds__(256,4): 4 CTAs/SM = 32 warps for latency hiding.
__global__ void __launch_bounds__(256, 4) k_gemm2e(int fin_sel,
                                                   const float* __restrict__ W,
                                                   int N, int K, int kchunk) {
    const float* fin = (fin_sel == 0) ? g_f0 : (fin_sel == 1) ? g_f1 : g_f2;
    int s = blockIdx.y;
    int t = threadIdx.x;
    int c0 = blockIdx.x * 512 + 2 * t;   // even
    int k0 = s * kchunk;
    int k1 = min(K, k0 + kchunk);
    bool v0 = (c0 < N);                  // N even: c0<N implies c0+1<N
    int ci = v0 ? c0 : 0;                // clamped even -> 8B aligned

    __shared__ __align__(16) float fs[128 * 16];   // [kk][b]
    unsigned long long acc[16];
#pragma unroll
    for (int p = 0; p < 16; p++) acc[p] = 0ull;

    for (int kt = k0; kt < k1; kt += 128) {
        int kc = min(128, k1 - kt);
        __syncthreads();
        for (int i = threadIdx.x; i < 16 * 128; i += 256) {
            int b = i >> 7, kk = i & 127;
            if (kk < kc) fs[kk * 16 + b] = fin[b * K + kt + kk];
        }
        __syncthreads();

        const float* wp = W + (size_t)kt * N;
#pragma unroll 8
        for (int kk = 0; kk < kc; kk++) {
            float2 wv = *(const float2*)(wp + (size_t)kk * N + ci);
            unsigned long long q0, q1;
            PACK2(q0, wv.x); PACK2(q1, wv.y);
            const ulonglong2* f4 = (const ulonglong2*)&fs[kk * 16];
            ulonglong2 r0 = f4[0], r1 = f4[1], r2 = f4[2], r3 = f4[3];
            FMA_F32X2(acc[0],  q0, r0.x); FMA_F32X2(acc[1],  q0, r0.y);
            FMA_F32X2(acc[2],  q0, r1.x); FMA_F32X2(acc[3],  q0, r1.y);
            FMA_F32X2(acc[4],  q0, r2.x); FMA_F32X2(acc[5],  q0, r2.y);
            FMA_F32X2(acc[6],  q0, r3.x); FMA_F32X2(acc[7],  q0, r3.y);
            FMA_F32X2(acc[8],  q1, r0.x); FMA_F32X2(acc[9],  q1, r0.y);
            FMA_F32X2(acc[10], q1, r1.x); FMA_F32X2(acc[11], q1, r1.y);
            FMA_F32X2(acc[12], q1, r2.x); FMA_F32X2(acc[13], q1, r2.y);
            FMA_F32X2(acc[14], q1, r3.x); FMA_F32X2(acc[15], q1, r3.y);
        }
    }

    if (v0) {
#pragma unroll
        for (int p = 0; p < 8; p++) {
            unsigned long long aL = acc[p], aH = acc[8 + p];
            float2 e, o2;
            e.x  = __uint_as_float((unsigned int)aL);
            e.y  = __uint_as_float((unsigned int)aH);
            o2.x = __uint_as_float((unsigned int)(aL >> 32));
            o2.y = __uint_as_float((unsigned int)(aH >> 32));
            *(float2*)&g_fcpart[(size_t)(s * 16 + 2 * p + 0) * N + c0] = e;
            *(float2*)&g_fcpart[(size_t)(s * 16 + 2 * p + 1) * N + c0] = o2;
        }
    }
}

// ---------------- FC GEMM (odd N: fc3) ----------------
// 2 cols per thread (stride 256), scalar LDG.32 loads, 16 u64 accs.
__global__ void __launch_bounds__(256, 4) k_gemm2o(int fin_sel,
                                                   const float* __restrict__ W,
                                                   int N, int K, int kchunk) {
    const float* fin = (fin_sel == 0) ? g_f0 : (fin_sel == 1) ? g_f1 : g_f2;
    int s = blockIdx.y;
    int t = threadIdx.x;
    int nbase = blockIdx.x * 512;
    int c0 = nbase + t, c1 = nbase + 256 + t;
    int k0 = s * kchunk;
    int k1 = min(K, k0 + kchunk);
    bool v0 = (c0 < N), v1 = (c1 < N);
    int i0 = v0 ? c0 : 0, i1 = v1 ? c1 : 0;

    __shared__ __align__(16) float fs[128 * 16];   // [kk][b]
    unsigned long long acc[16];
#pragma unroll
    for (int p = 0; p < 16; p++) acc[p] = 0ull;

    for (int kt = k0; kt < k1; kt += 128) {
        int kc = min(128, k1 - kt);
        __syncthreads();
        for (int i = threadIdx.x; i < 16 * 128; i += 256) {
            int b = i >> 7, kk = i & 127;
            if (kk < kc) fs[kk * 16 + b] = fin[b * K + kt + kk];
        }
        __syncthreads();

        const float* wp = W + (size_t)kt * N;
#pragma unroll 8
        for (int kk = 0; kk < kc; kk++) {
            const float* wr = wp + (size_t)kk * N;
            float w0 = wr[i0], w1 = wr[i1];
            unsigned long long q0, q1;
            PACK2(q0, w0); PACK2(q1, w1);
            const ulonglong2* f4 = (const ulonglong2*)&fs[kk * 16];
            ulonglong2 r0 = f4[0], r1 = f4[1], r2 = f4[2], r3 = f4[3];
            FMA_F32X2(acc[0],  q0, r0.x); FMA_F32X2(acc[1],  q0, r0.y);
            FMA_F32X2(acc[2],  q0, r1.x); FMA_F32X2(acc[3],  q0, r1.y);
            FMA_F32X2(acc[4],  q0, r2.x); FMA_F32X2(acc[5],  q0, r2.y);
            FMA_F32X2(acc[6],  q0, r3.x); FMA_F32X2(acc[7],  q0, r3.y);
            FMA_F32X2(acc[8],  q1, r0.x); FMA_F32X2(acc[9],  q1, r0.y);
            FMA_F32X2(acc[10], q1, r1.x); FMA_F32X2(acc[11], q1, r1.y);
            FMA_F32X2(acc[12], q1, r2.x); FMA_F32X2(acc[13], q1, r2.y);
            FMA_F32X2(acc[14], q1, r3.x); FMA_F32X2(acc[15], q1, r3.y);
        }
    }

    if (v0) {
#pragma unroll
        for (int p = 0; p < 8; p++) {
            unsigned long long a = acc[p];
            g_fcpart[(size_t)(s * 16 + 2 * p + 0) * N + c0] = __uint_as_float((unsigned int)a);
            g_fcpart[(size_t)(s * 16 + 2 * p + 1) * N + c0] = __uint_as_float((unsigned int)(a >> 32));
        }
    }
    if (v1) {
#pragma unroll
        for (int p = 0; p < 8; p++) {
            unsigned long long a = acc[8 + p];
            g_fcpart[(size_t)(s * 16 + 2 * p + 0) * N + c1] = __uint_as_float((unsigned int)a);
            g_fcpart[(size_t)(s * 16 + 2 * p + 1) * N + c1] = __uint_as_float((unsigned int)(a >> 32));
        }
    }
}

// deterministic k-split reduction + bias.
// out_sel: 0 -> g_f1, 1 -> g_f2, 2 -> harness out pointer (recon region)
__global__ void k_reduce(const float* __restrict__ bias,
                         int N, int S, int out_sel, float* __restrict__ hout) {
    float* out = (out_sel == 0) ? g_f1 : (out_sel == 1) ? g_f2 : hout;
    int idx = blockIdx.x * 256 + threadIdx.x;
    if (idx < 16 * N) {
        int b = idx / N, n = idx - b * N;
        float s = bias[n];
        for (int sp = 0; sp < S; sp++) s += g_fcpart[(size_t)(sp * 16 + b) * N + n];
        out[b * N + n] = s;
    }
}

// ---------------- launcher ----------------
extern "C" void kernel_launch(void* const* d_in, const int* in_sizes, int n_in,
                              void* d_out, int out_size) {
    const float* x      = (const float*)d_in[0];
    const float* conv_w = (const float*)d_in[1];
    const float* conv_b = (const float*)d_in[2];
    const float* W_caps = (const float*)d_in[3];
    const float* fc1_w  = (const float*)d_in[4];
    const float* fc1_b  = (const float*)d_in[5];
    const float* fc2_w  = (const float*)d_in[6];
    const float* fc2_b  = (const float*)d_in[7];
    const float* fc3_w  = (const float*)d_in[8];
    const float* fc3_b  = (const float*)d_in[9];
    float* out = (float*)d_out;

    (void)in_sizes; (void)n_in; (void)out_size;

    k_prep<<<(927 * 256 + NOUT * CCONV + 255) / 256, 256>>>(conv_w);
    k_wsum<<<1648, 256>>>(W_caps);
    k_conv<<<dim3(NCH, 16), 256>>>(x);
    k_relu_sum<<<(Bsz * CCONV * 49 + 255) / 256, 256>>>(conv_b);
    k_squash_p<<<16, 256>>>();

    for (int it = 0; it < 3; it++) {
        k_route_sj<<<103, 256>>>();
        k_route_v<<<16, 256>>>();
        if (it < 2) k_route_update<<<103, 256>>>();
    }
    k_ba_f0<<<7, 256>>>(out);

    // fc1: (16x1648)@(1648x5562)   tiles=11, S=26 (chunk 64)  -> 286 blocks  [even]
    k_gemm2e<<<dim3(11, 26), 256>>>(0, fc1_w, H1N, F0N, 64);
    k_reduce<<<(16 * H1N + 255) / 256, 256>>>(fc1_b, H1N, 26, 0, out);
    // fc2: (16x5562)@(5562x12514)  tiles=25, S=23 (chunk 242) -> 575 blocks  [even]
    k_gemm2e<<<dim3(25, 23), 256>>>(1, fc2_w, H2N, H1N, 242);
    k_reduce<<<(16 * H2N + 255) / 256, 256>>>(fc2_b, H2N, 23, 1, out);
    // fc3: (16x12514)@(12514x8343) tiles=17, S=33 (chunk 380) -> 561 blocks  [odd]
    k_gemm2o<<<dim3(17, 33), 256>>>(2, fc3_w, RECN, H2N, 380);
    k_reduce<<<(16 * RECN + 255) / 256, 256>>>(fc3_b, RECN, 33, 2, out + Bsz * NOUT);
}